// round 14
// baseline (speedup 1.0000x reference)
#include <cuda_runtime.h>
#include <cstdint>

#define T     2048
#define E     512
#define HD    512
#define G4    2048   /* 4*HD */
#define TAGS  32
#define START 30
#define STOP  31
#define NEGV  (-10000.0f)

#define CANARY 0xFFFFFFFFu

// ---------------- scratch (device globals; no allocation) ----------------
__device__ float g_x[T * E];          // gathered embeddings          4 MB
__device__ float g_xg[2][T * G4];     // precomputed input gates     32 MB
__device__ float g_h[2][T * HD];      // LSTM hidden outputs          8 MB
__device__ float g_feats[T * TAGS];   // emissions                  256 KB
__device__ float g_fv[(T + 1) * TAGS];// viterbi fv trajectory      262 KB
__device__ unsigned g_vit_done;       // heater shutdown flag

// ---------------- gather + poison fused ----------------
__global__ void k_prep(const int* __restrict__ sent, const float* __restrict__ emb) {
    int blk = blockIdx.x;
    if (blk == 0 && threadIdx.x == 0) g_vit_done = 0;   // reset every launch
    if (blk < T) {
        const float4* src = (const float4*)(emb + (size_t)sent[blk] * E);
        ((float4*)(g_x + (size_t)blk * E))[threadIdx.x] = src[threadIdx.x];
    } else {
        int cb = blk - T;
        unsigned* dst = (unsigned*)g_h + (size_t)cb * 1024 + threadIdx.x * 8;
        uint4 v = {CANARY, CANARY, CANARY, CANARY};
        *(uint4*)(dst)     = v;
        *(uint4*)(dst + 4) = v;
    }
}

// ---------------- packed f32x2 helpers ----------------
#define FMA2(acc, a, b) asm("fma.rn.f32x2 %0, %1, %2, %0;" : "+l"(acc) : "l"(a), "l"(b))
#define ADD2(acc, b)    asm("add.rn.f32x2 %0, %0, %1;" : "+l"(acc) : "l"(b))
#define ADD2O(out, a, b) asm("add.rn.f32x2 %0, %1, %2;" : "=l"(out) : "l"(a), "l"(b))
#define PACK2(out, lo, hi) asm("mov.b64 %0, {%1, %2};" : "=l"(out) : "f"(lo), "f"(hi))
#define UNPK2(lo, hi, pk)  asm("mov.b64 {%0, %1}, %2;" : "=f"(lo), "=f"(hi) : "l"(pk))

// ---------------- input GEMM: g_xg[d] = g_x @ W_ih[d]^T + b[d] (FFMA2) -------
#define BM 128
#define BN 128
#define BK 16
__global__ void __launch_bounds__(256) k_gemm(const float* __restrict__ w_ih_f,
                                              const float* __restrict__ b_f,
                                              const float* __restrict__ w_ih_b,
                                              const float* __restrict__ b_b) {
    int d = blockIdx.z;
    const float* W    = d ? w_ih_b : w_ih_f;
    const float* bias = d ? b_b    : b_f;

    __shared__ float As[BK][BM];
    __shared__ float Bs[BK][BN];

    int tid = threadIdx.x;
    int tx = tid & 15, ty = tid >> 4;
    int t0 = blockIdx.y * BM, r0 = blockIdx.x * BN;

    unsigned long long acc2[8][4];
#pragma unroll
    for (int i = 0; i < 8; i++)
#pragma unroll
        for (int j = 0; j < 4; j++) acc2[i][j] = 0ull;

    int lm = tid >> 2;            // 0..63
    int lk = (tid & 3) * 4;       // 0,4,8,12

    for (int k0 = 0; k0 < E; k0 += BK) {
#pragma unroll
        for (int rep = 0; rep < 2; rep++) {
            float4 v = *(const float4*)(g_x + (size_t)(t0 + lm + rep * 64) * E + k0 + lk);
            As[lk + 0][lm + rep * 64] = v.x;
            As[lk + 1][lm + rep * 64] = v.y;
            As[lk + 2][lm + rep * 64] = v.z;
            As[lk + 3][lm + rep * 64] = v.w;
            float4 w = *(const float4*)(W + (size_t)(r0 + lm + rep * 64) * E + k0 + lk);
            Bs[lk + 0][lm + rep * 64] = w.x;
            Bs[lk + 1][lm + rep * 64] = w.y;
            Bs[lk + 2][lm + rep * 64] = w.z;
            Bs[lk + 3][lm + rep * 64] = w.w;
        }
        __syncthreads();
#pragma unroll
        for (int k = 0; k < BK; k++) {
            float a[8];
            *(float4*)(a)     = *(const float4*)&As[k][ty * 8];
            *(float4*)(a + 4) = *(const float4*)&As[k][ty * 8 + 4];
            ulonglong2 bl = *(const ulonglong2*)&Bs[k][tx * 8];
            ulonglong2 bh = *(const ulonglong2*)&Bs[k][tx * 8 + 4];
            unsigned long long bq[4] = {bl.x, bl.y, bh.x, bh.y};
#pragma unroll
            for (int i = 0; i < 8; i++) {
                unsigned long long ad;
                PACK2(ad, a[i], a[i]);
                FMA2(acc2[i][0], ad, bq[0]);
                FMA2(acc2[i][1], ad, bq[1]);
                FMA2(acc2[i][2], ad, bq[2]);
                FMA2(acc2[i][3], ad, bq[3]);
            }
        }
        __syncthreads();
    }

    float* out = g_xg[d];
#pragma unroll
    for (int i = 0; i < 8; i++) {
        int t = t0 + ty * 8 + i;
#pragma unroll
        for (int jp = 0; jp < 4; jp += 2) {
            int r = r0 + tx * 8 + jp * 2;
            float4 v;
            v.x = __uint_as_float((unsigned)(acc2[i][jp]     & 0xFFFFFFFFull)) + bias[r + 0];
            v.y = __uint_as_float((unsigned)(acc2[i][jp]     >> 32))           + bias[r + 1];
            v.z = __uint_as_float((unsigned)(acc2[i][jp + 1] & 0xFFFFFFFFull)) + bias[r + 2];
            v.w = __uint_as_float((unsigned)(acc2[i][jp + 1] >> 32))           + bias[r + 3];
            *(float4*)(out + (size_t)t * G4 + r) = v;
        }
    }
}

// ---------------- persistent bidirectional LSTM recurrence (R7, proven) ------
__device__ __forceinline__ float sig_f(float x) {
    return __fdividef(1.f, 1.f + __expf(-x));
}
__device__ __forceinline__ float tanh_f(float x) {
    return 1.f - __fdividef(2.f, __expf(2.f * x) + 1.f);
}

__global__ void __launch_bounds__(288, 1) k_lstm(const float* __restrict__ w_hh_f,
                                                 const float* __restrict__ w_hh_b,
                                                 const float* __restrict__ h0,
                                                 const float* __restrict__ c0) {
    int cta = blockIdx.x;
    int d = cta >> 6;
    int b = cta & 63;
    const float* Whh = d ? w_hh_b : w_hh_f;

    int tid  = threadIdx.x;
    int wid  = tid >> 5;
    int lane = tid & 31;

    __shared__ float sh_h[HD];
    __shared__ float sh_part[8 * 32];

    float* hout = g_h[d];

    if (wid < 8) {
        // ---------------- producer warp ----------------
        int seg  = wid;
        int gate = lane >> 3, jj = lane & 7;
        int grow = gate * HD + b * 8 + jj;

        unsigned long long wq[32];
        {
            const ulonglong2* wr = (const ulonglong2*)(Whh + (size_t)grow * HD + seg * 64);
#pragma unroll
            for (int m = 0; m < 16; m++) {
                ulonglong2 v = wr[m];
                wq[2 * m] = v.x; wq[2 * m + 1] = v.y;
            }
        }

        for (int s = 0; s < T; s++) {
            int t = d ? (T - 1 - s) : s;
            float2 hv;
            if (s == 0) {
                hv = *(const float2*)(h0 + d * HD + seg * 64 + lane * 2);
            } else {
                int tp = d ? (t + 1) : (t - 1);
                const float* hp = hout + (size_t)tp * HD + seg * 64 + lane * 2;
                unsigned a, bb;
                do {
                    asm volatile("ld.volatile.global.v2.u32 {%0, %1}, [%2];"
                                 : "=r"(a), "=r"(bb) : "l"(hp));
                } while (a == CANARY || bb == CANARY);
                hv.x = __uint_as_float(a);
                hv.y = __uint_as_float(bb);
            }
            sh_h[seg * 64 + lane * 2]     = hv.x;
            sh_h[seg * 64 + lane * 2 + 1] = hv.y;
            __syncwarp();

            unsigned long long a0 = 0, a1 = 0, a2 = 0, a3 = 0;
            const ulonglong2* hq = (const ulonglong2*)(sh_h + seg * 64);
#pragma unroll
            for (int m = 0; m < 16; m += 2) {
                ulonglong2 x = hq[m];
                ulonglong2 y = hq[m + 1];
                FMA2(a0, wq[2 * m],     x.x);
                FMA2(a1, wq[2 * m + 1], x.y);
                FMA2(a2, wq[2 * m + 2], y.x);
                FMA2(a3, wq[2 * m + 3], y.y);
            }
            ADD2(a0, a2);
            ADD2(a1, a3);
            ADD2(a0, a1);
            float part = __uint_as_float((unsigned)(a0 & 0xFFFFFFFFull)) +
                         __uint_as_float((unsigned)(a0 >> 32));
            sh_part[seg * 32 + lane] = part;
            asm volatile("bar.arrive 1, 288;");
        }
    } else {
        // ---------------- reducer warp ----------------
        int gate = lane >> 3, jj = lane & 7;
        int grow = gate * HD + b * 8 + jj;
        const float* xg = g_xg[d];

        float c = 0.f;
        if (lane < 8) c = c0[d * HD + b * 8 + lane];

        int t0i = d ? (T - 1) : 0;
        float xg_cur = __ldg(xg + (size_t)t0i * G4 + grow);

        for (int s = 0; s < T; s++) {
            int t = d ? (T - 1 - s) : s;
            asm volatile("bar.sync 1, 288;");

            float xg_use = xg_cur;
            if (s + 1 < T) {
                int tn = d ? (t - 1) : (t + 1);
                xg_cur = __ldg(xg + (size_t)tn * G4 + grow);
            }

            float t0a = sh_part[0 * 32 + lane] + sh_part[1 * 32 + lane];
            float t1a = sh_part[2 * 32 + lane] + sh_part[3 * 32 + lane];
            float t2a = sh_part[4 * 32 + lane] + sh_part[5 * 32 + lane];
            float t3a = sh_part[6 * 32 + lane] + sh_part[7 * 32 + lane];
            float tot = xg_use + ((t0a + t1a) + (t2a + t3a));

            unsigned m = 0xFFFFFFFFu;
            float xi  = __shfl_sync(m, tot, (lane & 7));
            float xf  = __shfl_sync(m, tot, 8 + (lane & 7));
            float xgg = __shfl_sync(m, tot, 16 + (lane & 7));
            float xo  = __shfl_sync(m, tot, 24 + (lane & 7));
            if (lane < 8) {
                c = sig_f(xf) * c + sig_f(xi) * tanh_f(xgg);
                float hnew = sig_f(xo) * tanh_f(c);
                asm volatile("st.volatile.global.f32 [%0], %1;"
                             :: "l"(hout + (size_t)t * HD + b * 8 + lane), "f"(hnew));
            }
        }
    }
}

// ---------------- emissions: feats = [hf|hb] @ W_out^T + b_out ----------------
#define FB 16
__global__ void __launch_bounds__(512) k_feats(const float* __restrict__ W_out,
                                               const float* __restrict__ b_out) {
    __shared__ float shp[16 * 68];   // single array: 1024 cols padded to 1088

    int tid = threadIdx.x;
    int tag = tid >> 4, q = tid & 15;

    float4 wr[16];
    const float4* wp = (const float4*)(W_out + (size_t)tag * 1024 + q * 64);
#pragma unroll
    for (int i = 0; i < 16; i++) wr[i] = wp[i];
    float bias = b_out[tag];

    int c  = tid * 2;
    int cs = (c >> 6) * 68 + (c & 63);
    int t0 = blockIdx.x * FB;

    for (int i = 0; i < FB; i++) {
        int t = t0 + i;
        const float* src = (c < 512) ? (g_h[0] + (size_t)t * HD + c)
                                     : (g_h[1] + (size_t)t * HD + (c - 512));
        float2 hv = *(const float2*)src;
        __syncthreads();
        shp[cs]     = hv.x;
        shp[cs + 1] = hv.y;
        __syncthreads();

        const float4* hq = (const float4*)&shp[q * 68];
        float s = 0.f;
#pragma unroll
        for (int k2 = 0; k2 < 16; k2++) {
            float4 h4 = hq[k2];
            float4 w4 = wr[k2];
            s += w4.x * h4.x + w4.y * h4.y + w4.z * h4.z + w4.w * h4.w;
        }
        s += __shfl_xor_sync(0xFFFFFFFFu, s, 1);
        s += __shfl_xor_sync(0xFFFFFFFFu, s, 2);
        s += __shfl_xor_sync(0xFFFFFFFFu, s, 4);
        s += __shfl_xor_sync(0xFFFFFFFFu, s, 8);
        if (q == 0) g_feats[t * TAGS + tag] = s + bias;
    }
}

// ---------------- Viterbi v8: v7 phases + HEATER blocks (DVFS test) ----------
// Block 0: race-free phase-separated viterbi (R13, rel_err 0.0).
// Blocks 1-147: FFMA heaters keeping all SMs issuing -> hold boost clocks
// while the single serial warp runs. Heaters poll g_vit_done (~every 512
// FMA), iteration-capped for guaranteed termination. Smem padded to 128KB
// forces 1 block/SM so no heater shares block 0's SM.
#define VOFF_STAGE 65536                  /* bp = [0, 65536) */
#define VOFF_PP    (VOFF_STAGE + 32 * 32 * 4)
#define VSM_TOTAL  (128 * 1024)           /* pad: force 1 block per SM */

extern __shared__ unsigned char vsm[];
__global__ void __launch_bounds__(1024, 1) k_vit(const float* __restrict__ transitions,
                                                 float* __restrict__ out, int out_size) {
    if (blockIdx.x != 0) {
        // ---------------- heater block ----------------
        float a0 = 1.000001f + threadIdx.x * 1e-7f, a1 = 0.999999f;
        float a2 = 1.0000005f, a3 = 0.9999995f;
        const float b0 = 1.0000002f, b1 = 0.9999998f;
        const float b2 = 1.0000001f, b3 = 0.9999999f;
        for (int it = 0; it < 20000; it++) {       // cap ≈ few ms worst case
#pragma unroll
            for (int i = 0; i < 128; i++) {
                a0 = fmaf(a0, b0, 1e-7f);
                a1 = fmaf(a1, b1, 1e-7f);
                a2 = fmaf(a2, b2, 1e-7f);
                a3 = fmaf(a3, b3, 1e-7f);
            }
            asm volatile("" :: "f"(a0), "f"(a1), "f"(a2), "f"(a3));
            unsigned done;
            asm volatile("ld.volatile.global.u32 %0, [%1];" : "=r"(done) : "l"(&g_vit_done));
            if (done) break;
        }
        return;
    }

    unsigned char* bp = vsm;
    float* stage = (float*)(vsm + VOFF_STAGE);   // [32 warps][32]
    float* pp    = (float*)(vsm + VOFF_PP);      // [2][32]

    int tid = threadIdx.x;
    int w = tid >> 5, n = tid & 31;

    // ---------------- Phase 1: forward (warp 31 only) ----------------
    if (w == 31) {
        unsigned long long trq[16];
        {
            const ulonglong2* tp = (const ulonglong2*)(transitions + n * TAGS);
#pragma unroll
            for (int p = 0; p < 8; p++) {
                ulonglong2 v = tp[p];
                trq[2 * p] = v.x; trq[2 * p + 1] = v.y;
            }
        }

        float fr[8];
#pragma unroll
        for (int i = 0; i < 8; i++) fr[i] = __ldg(g_feats + i * TAGS + n);

        float fv = (n == START) ? 0.f : NEGV;

        for (int tb = 0; tb < T; tb += 8) {
#pragma unroll
            for (int i = 0; i < 8; i++) {
                int t = tb + i;
                int pb = (t & 1) * 32;
                pp[pb + n] = fv;
                g_fv[t * TAGS + n] = fv;
                __syncwarp();

                const ulonglong2* fq = (const ulonglong2*)(pp + pb);
                float m0, m1, m2, m3;
                {
                    ulonglong2 q0 = fq[0], q1 = fq[1];
                    unsigned long long s0, s1, s2, s3;
                    ADD2O(s0, q0.x, trq[0]);
                    ADD2O(s1, q0.y, trq[1]);
                    ADD2O(s2, q1.x, trq[2]);
                    ADD2O(s3, q1.y, trq[3]);
                    float a, b;
                    UNPK2(a, b, s0); m0 = fmaxf(a, b);
                    UNPK2(a, b, s1); m1 = fmaxf(a, b);
                    UNPK2(a, b, s2); m2 = fmaxf(a, b);
                    UNPK2(a, b, s3); m3 = fmaxf(a, b);
                }
#pragma unroll
                for (int p = 2; p < 8; p += 2) {
                    ulonglong2 qa = fq[p], qb = fq[p + 1];
                    unsigned long long s0, s1, s2, s3;
                    ADD2O(s0, qa.x, trq[2 * p]);
                    ADD2O(s1, qa.y, trq[2 * p + 1]);
                    ADD2O(s2, qb.x, trq[2 * p + 2]);
                    ADD2O(s3, qb.y, trq[2 * p + 3]);
                    float a, b;
                    UNPK2(a, b, s0); m0 = fmaxf(m0, a); m0 = fmaxf(m0, b);
                    UNPK2(a, b, s1); m1 = fmaxf(m1, a); m1 = fmaxf(m1, b);
                    UNPK2(a, b, s2); m2 = fmaxf(m2, a); m2 = fmaxf(m2, b);
                    UNPK2(a, b, s3); m3 = fmaxf(m3, a); m3 = fmaxf(m3, b);
                }
                float best = fmaxf(fmaxf(m0, m1), fmaxf(m2, m3));

                float feat = fr[i];
                if (t + 8 < T) fr[i] = __ldg(g_feats + (t + 8) * TAGS + n);
                fv = best + feat;
            }
        }
        g_fv[T * TAGS + n] = fv;
    }

    __syncthreads();

    // ---------------- Phase 2: backpointers (all 32 warps, prefetched) -------
    {
        float tr[TAGS];
#pragma unroll
        for (int j = 0; j < TAGS; j++) tr[j] = transitions[n * TAGS + j];

        float* st = stage + w * TAGS;
        int tbeg = w * 64;
        float cur = __ldg(g_fv + (size_t)tbeg * TAGS + n);
        for (int t = tbeg; t < tbeg + 64; t++) {
            st[n] = cur;
            __syncwarp();
            float nxt = (t + 1 < tbeg + 64) ? __ldg(g_fv + (size_t)(t + 1) * TAGS + n) : 0.f;

            float bbest = st[0] + tr[0];
            int   barg  = 0;
#pragma unroll
            for (int j = 1; j < 32; j++) {
                float s = st[j] + tr[j];
                if (s > bbest) { bbest = s; barg = j; }
            }
            bp[t * TAGS + n] = (unsigned char)barg;
            __syncwarp();
            cur = nxt;
        }
    }

    __syncthreads();

    // ---------------- Phase 3: terminal + backtrack + heater shutdown --------
    if (tid == 0) {
        int best = 0;
        float bb = g_fv[T * TAGS + 0] + transitions[STOP * TAGS + 0];
#pragma unroll
        for (int j = 1; j < TAGS; j++) {
            float v = g_fv[T * TAGS + j] + transitions[STOP * TAGS + j];
            if (v > bb) { bb = v; best = j; }
        }
        float score = g_fv[T * TAGS + best] + transitions[STOP * TAGS + best];

        if (out_size >= T + 1) {
            out[0] = score;
            int tag = best;
            for (int t = T - 1; t >= 0; t--) {
                out[1 + t] = (float)tag;
                tag = bp[t * TAGS + tag];
            }
        } else if (out_size >= T) {
            int tag = best;
            for (int t = T - 1; t >= 0; t--) {
                out[t] = (float)tag;
                tag = bp[t * TAGS + tag];
            }
        } else {
            out[0] = score;
        }

        __threadfence();
        asm volatile("st.volatile.global.u32 [%0], %1;" :: "l"(&g_vit_done), "r"(1u));
    }
}

// ---------------- launch ----------------
extern "C" void kernel_launch(void* const* d_in, const int* in_sizes, int n_in,
                              void* d_out, int out_size) {
    const int*   sentence    = (const int*)d_in[0];
    const float* emb         = (const float*)d_in[1];
    const float* w_ih_f      = (const float*)d_in[2];
    const float* w_hh_f      = (const float*)d_in[3];
    const float* b_f         = (const float*)d_in[4];
    const float* w_ih_b      = (const float*)d_in[5];
    const float* w_hh_b      = (const float*)d_in[6];
    const float* b_b         = (const float*)d_in[7];
    const float* W_out       = (const float*)d_in[8];
    const float* b_out       = (const float*)d_in[9];
    const float* transitions = (const float*)d_in[10];
    const float* h0          = (const float*)d_in[11];
    const float* c0          = (const float*)d_in[12];
    float* out = (float*)d_out;

    k_prep<<<T + 2048, 128>>>(sentence, emb);
    k_gemm<<<dim3(16, 16, 2), 256>>>(w_ih_f, b_f, w_ih_b, b_b);
    k_lstm<<<128, 288>>>(w_hh_f, w_hh_b, h0, c0);
    k_feats<<<128, 512>>>(W_out, b_out);

    cudaFuncSetAttribute(k_vit, cudaFuncAttributeMaxDynamicSharedMemorySize, VSM_TOTAL);
    k_vit<<<148, 1024, VSM_TOTAL>>>(transitions, out, out_size);
}

// round 15
// speedup vs baseline: 1.3371x; 1.3371x over previous
#include <cuda_runtime.h>
#include <cstdint>

#define T     2048
#define E     512
#define HD    512
#define G4    2048   /* 4*HD */
#define TAGS  32
#define START 30
#define STOP  31
#define NEGV  (-10000.0f)

#define CANARY 0xFFFFFFFFu

// ---------------- scratch (device globals; no allocation) ----------------
__device__ float g_x[T * E];          // gathered embeddings          4 MB
__device__ float g_xg[2][T * G4];     // precomputed input gates     32 MB
__device__ float g_h[2][T * HD];      // LSTM hidden outputs          8 MB
__device__ float g_feats[T * TAGS];   // emissions                  256 KB
__device__ float g_fv[(T + 1) * TAGS];// viterbi fv trajectory      262 KB

// ---------------- gather + poison fused ----------------
__global__ void k_prep(const int* __restrict__ sent, const float* __restrict__ emb) {
    int blk = blockIdx.x;
    if (blk < T) {
        const float4* src = (const float4*)(emb + (size_t)sent[blk] * E);
        ((float4*)(g_x + (size_t)blk * E))[threadIdx.x] = src[threadIdx.x];
    } else {
        int cb = blk - T;
        unsigned* dst = (unsigned*)g_h + (size_t)cb * 1024 + threadIdx.x * 8;
        uint4 v = {CANARY, CANARY, CANARY, CANARY};
        *(uint4*)(dst)     = v;
        *(uint4*)(dst + 4) = v;
    }
}

// ---------------- packed f32x2 helpers ----------------
#define FMA2(acc, a, b) asm("fma.rn.f32x2 %0, %1, %2, %0;" : "+l"(acc) : "l"(a), "l"(b))
#define ADD2(acc, b)    asm("add.rn.f32x2 %0, %0, %1;" : "+l"(acc) : "l"(b))
#define ADD2O(out, a, b) asm("add.rn.f32x2 %0, %1, %2;" : "=l"(out) : "l"(a), "l"(b))
#define PACK2(out, lo, hi) asm("mov.b64 %0, {%1, %2};" : "=l"(out) : "f"(lo), "f"(hi))
#define UNPK2(lo, hi, pk)  asm("mov.b64 {%0, %1}, %2;" : "=f"(lo), "=f"(hi) : "l"(pk))

// ---------------- input GEMM: g_xg[d] = g_x @ W_ih[d]^T + b[d] (FFMA2) -------
#define BM 128
#define BN 128
#define BK 16
__global__ void __launch_bounds__(256) k_gemm(const float* __restrict__ w_ih_f,
                                              const float* __restrict__ b_f,
                                              const float* __restrict__ w_ih_b,
                                              const float* __restrict__ b_b) {
    int d = blockIdx.z;
    const float* W    = d ? w_ih_b : w_ih_f;
    const float* bias = d ? b_b    : b_f;

    __shared__ float As[BK][BM];
    __shared__ float Bs[BK][BN];

    int tid = threadIdx.x;
    int tx = tid & 15, ty = tid >> 4;
    int t0 = blockIdx.y * BM, r0 = blockIdx.x * BN;

    unsigned long long acc2[8][4];
#pragma unroll
    for (int i = 0; i < 8; i++)
#pragma unroll
        for (int j = 0; j < 4; j++) acc2[i][j] = 0ull;

    int lm = tid >> 2;            // 0..63
    int lk = (tid & 3) * 4;       // 0,4,8,12

    for (int k0 = 0; k0 < E; k0 += BK) {
#pragma unroll
        for (int rep = 0; rep < 2; rep++) {
            float4 v = *(const float4*)(g_x + (size_t)(t0 + lm + rep * 64) * E + k0 + lk);
            As[lk + 0][lm + rep * 64] = v.x;
            As[lk + 1][lm + rep * 64] = v.y;
            As[lk + 2][lm + rep * 64] = v.z;
            As[lk + 3][lm + rep * 64] = v.w;
            float4 w = *(const float4*)(W + (size_t)(r0 + lm + rep * 64) * E + k0 + lk);
            Bs[lk + 0][lm + rep * 64] = w.x;
            Bs[lk + 1][lm + rep * 64] = w.y;
            Bs[lk + 2][lm + rep * 64] = w.z;
            Bs[lk + 3][lm + rep * 64] = w.w;
        }
        __syncthreads();
#pragma unroll
        for (int k = 0; k < BK; k++) {
            float a[8];
            *(float4*)(a)     = *(const float4*)&As[k][ty * 8];
            *(float4*)(a + 4) = *(const float4*)&As[k][ty * 8 + 4];
            ulonglong2 bl = *(const ulonglong2*)&Bs[k][tx * 8];
            ulonglong2 bh = *(const ulonglong2*)&Bs[k][tx * 8 + 4];
            unsigned long long bq[4] = {bl.x, bl.y, bh.x, bh.y};
#pragma unroll
            for (int i = 0; i < 8; i++) {
                unsigned long long ad;
                PACK2(ad, a[i], a[i]);
                FMA2(acc2[i][0], ad, bq[0]);
                FMA2(acc2[i][1], ad, bq[1]);
                FMA2(acc2[i][2], ad, bq[2]);
                FMA2(acc2[i][3], ad, bq[3]);
            }
        }
        __syncthreads();
    }

    float* out = g_xg[d];
#pragma unroll
    for (int i = 0; i < 8; i++) {
        int t = t0 + ty * 8 + i;
#pragma unroll
        for (int jp = 0; jp < 4; jp += 2) {
            int r = r0 + tx * 8 + jp * 2;
            float4 v;
            v.x = __uint_as_float((unsigned)(acc2[i][jp]     & 0xFFFFFFFFull)) + bias[r + 0];
            v.y = __uint_as_float((unsigned)(acc2[i][jp]     >> 32))           + bias[r + 1];
            v.z = __uint_as_float((unsigned)(acc2[i][jp + 1] & 0xFFFFFFFFull)) + bias[r + 2];
            v.w = __uint_as_float((unsigned)(acc2[i][jp + 1] >> 32))           + bias[r + 3];
            *(float4*)(out + (size_t)t * G4 + r) = v;
        }
    }
}

// ---------------- persistent bidirectional LSTM recurrence (R7, proven) ------
__device__ __forceinline__ float sig_f(float x) {
    return __fdividef(1.f, 1.f + __expf(-x));
}
__device__ __forceinline__ float tanh_f(float x) {
    return 1.f - __fdividef(2.f, __expf(2.f * x) + 1.f);
}

__global__ void __launch_bounds__(288, 1) k_lstm(const float* __restrict__ w_hh_f,
                                                 const float* __restrict__ w_hh_b,
                                                 const float* __restrict__ h0,
                                                 const float* __restrict__ c0) {
    int cta = blockIdx.x;
    int d = cta >> 6;
    int b = cta & 63;
    const float* Whh = d ? w_hh_b : w_hh_f;

    int tid  = threadIdx.x;
    int wid  = tid >> 5;
    int lane = tid & 31;

    __shared__ float sh_h[HD];
    __shared__ float sh_part[8 * 32];

    float* hout = g_h[d];

    if (wid < 8) {
        // ---------------- producer warp ----------------
        int seg  = wid;
        int gate = lane >> 3, jj = lane & 7;
        int grow = gate * HD + b * 8 + jj;

        unsigned long long wq[32];
        {
            const ulonglong2* wr = (const ulonglong2*)(Whh + (size_t)grow * HD + seg * 64);
#pragma unroll
            for (int m = 0; m < 16; m++) {
                ulonglong2 v = wr[m];
                wq[2 * m] = v.x; wq[2 * m + 1] = v.y;
            }
        }

        for (int s = 0; s < T; s++) {
            int t = d ? (T - 1 - s) : s;
            float2 hv;
            if (s == 0) {
                hv = *(const float2*)(h0 + d * HD + seg * 64 + lane * 2);
            } else {
                int tp = d ? (t + 1) : (t - 1);
                const float* hp = hout + (size_t)tp * HD + seg * 64 + lane * 2;
                unsigned a, bb;
                do {
                    asm volatile("ld.volatile.global.v2.u32 {%0, %1}, [%2];"
                                 : "=r"(a), "=r"(bb) : "l"(hp));
                } while (a == CANARY || bb == CANARY);
                hv.x = __uint_as_float(a);
                hv.y = __uint_as_float(bb);
            }
            sh_h[seg * 64 + lane * 2]     = hv.x;
            sh_h[seg * 64 + lane * 2 + 1] = hv.y;
            __syncwarp();

            unsigned long long a0 = 0, a1 = 0, a2 = 0, a3 = 0;
            const ulonglong2* hq = (const ulonglong2*)(sh_h + seg * 64);
#pragma unroll
            for (int m = 0; m < 16; m += 2) {
                ulonglong2 x = hq[m];
                ulonglong2 y = hq[m + 1];
                FMA2(a0, wq[2 * m],     x.x);
                FMA2(a1, wq[2 * m + 1], x.y);
                FMA2(a2, wq[2 * m + 2], y.x);
                FMA2(a3, wq[2 * m + 3], y.y);
            }
            ADD2(a0, a2);
            ADD2(a1, a3);
            ADD2(a0, a1);
            float part = __uint_as_float((unsigned)(a0 & 0xFFFFFFFFull)) +
                         __uint_as_float((unsigned)(a0 >> 32));
            sh_part[seg * 32 + lane] = part;
            asm volatile("bar.arrive 1, 288;");
        }
    } else {
        // ---------------- reducer warp ----------------
        int gate = lane >> 3, jj = lane & 7;
        int grow = gate * HD + b * 8 + jj;
        const float* xg = g_xg[d];

        float c = 0.f;
        if (lane < 8) c = c0[d * HD + b * 8 + lane];

        int t0i = d ? (T - 1) : 0;
        float xg_cur = __ldg(xg + (size_t)t0i * G4 + grow);

        for (int s = 0; s < T; s++) {
            int t = d ? (T - 1 - s) : s;
            asm volatile("bar.sync 1, 288;");

            float xg_use = xg_cur;
            if (s + 1 < T) {
                int tn = d ? (t - 1) : (t + 1);
                xg_cur = __ldg(xg + (size_t)tn * G4 + grow);
            }

            float t0a = sh_part[0 * 32 + lane] + sh_part[1 * 32 + lane];
            float t1a = sh_part[2 * 32 + lane] + sh_part[3 * 32 + lane];
            float t2a = sh_part[4 * 32 + lane] + sh_part[5 * 32 + lane];
            float t3a = sh_part[6 * 32 + lane] + sh_part[7 * 32 + lane];
            float tot = xg_use + ((t0a + t1a) + (t2a + t3a));

            unsigned m = 0xFFFFFFFFu;
            float xi  = __shfl_sync(m, tot, (lane & 7));
            float xf  = __shfl_sync(m, tot, 8 + (lane & 7));
            float xgg = __shfl_sync(m, tot, 16 + (lane & 7));
            float xo  = __shfl_sync(m, tot, 24 + (lane & 7));
            if (lane < 8) {
                c = sig_f(xf) * c + sig_f(xi) * tanh_f(xgg);
                float hnew = sig_f(xo) * tanh_f(c);
                asm volatile("st.volatile.global.f32 [%0], %1;"
                             :: "l"(hout + (size_t)t * HD + b * 8 + lane), "f"(hnew));
            }
        }
    }
}

// ---------------- emissions: feats = [hf|hb] @ W_out^T + b_out ----------------
#define FB 16
__global__ void __launch_bounds__(512) k_feats(const float* __restrict__ W_out,
                                               const float* __restrict__ b_out) {
    __shared__ float shp[16 * 68];   // single array: 1024 cols padded to 1088

    int tid = threadIdx.x;
    int tag = tid >> 4, q = tid & 15;

    float4 wr[16];
    const float4* wp = (const float4*)(W_out + (size_t)tag * 1024 + q * 64);
#pragma unroll
    for (int i = 0; i < 16; i++) wr[i] = wp[i];
    float bias = b_out[tag];

    int c  = tid * 2;
    int cs = (c >> 6) * 68 + (c & 63);
    int t0 = blockIdx.x * FB;

    for (int i = 0; i < FB; i++) {
        int t = t0 + i;
        const float* src = (c < 512) ? (g_h[0] + (size_t)t * HD + c)
                                     : (g_h[1] + (size_t)t * HD + (c - 512));
        float2 hv = *(const float2*)src;
        __syncthreads();
        shp[cs]     = hv.x;
        shp[cs + 1] = hv.y;
        __syncthreads();

        const float4* hq = (const float4*)&shp[q * 68];
        float s = 0.f;
#pragma unroll
        for (int k2 = 0; k2 < 16; k2++) {
            float4 h4 = hq[k2];
            float4 w4 = wr[k2];
            s += w4.x * h4.x + w4.y * h4.y + w4.z * h4.z + w4.w * h4.w;
        }
        s += __shfl_xor_sync(0xFFFFFFFFu, s, 1);
        s += __shfl_xor_sync(0xFFFFFFFFu, s, 2);
        s += __shfl_xor_sync(0xFFFFFFFFu, s, 4);
        s += __shfl_xor_sync(0xFFFFFFFFu, s, 8);
        if (q == 0) g_feats[t * TAGS + tag] = s + bias;
    }
}

// ---------------- Viterbi v9: phase-separated, all-smem serial loop ----------
// 1 working CTA x 1024 (grid 148, other blocks exit; ~196KB smem -> 1 CTA/SM).
// Half A load (all warps) -> barrier -> forward t=0..1023 (warp 31 alone;
// feat via LDS pipelined 1 ahead; ONLY global op is fire-and-forget STG of
// the fv trajectory) -> barrier -> half B load -> forward t=1024..2047 ->
// barrier -> Phase 2: all 32 warps recompute exact first-max backpointers
// from g_fv (prefetched LDG) -> Phase 3: terminal + smem backtrack.
// No flags, no polling, no heaters. Exact jnp semantics throughout.
#define VOFF_FBUF  65536                      /* bp = [0, 65536) */
#define VOFF_STAGE (VOFF_FBUF + 1024 * 32 * 4)
#define VOFF_PP    (VOFF_STAGE + 32 * 32 * 4)
#define VSM_TOTAL  (VOFF_PP + 2 * 32 * 4)     /* 200,960 B */

extern __shared__ unsigned char vsm[];
__global__ void __launch_bounds__(1024, 1) k_vit(const float* __restrict__ transitions,
                                                 float* __restrict__ out, int out_size) {
    if (blockIdx.x != 0) return;

    unsigned char* bp = vsm;
    float* fbuf  = (float*)(vsm + VOFF_FBUF);    // [1024][32]
    float* stage = (float*)(vsm + VOFF_STAGE);   // [32 warps][32]
    float* pp    = (float*)(vsm + VOFF_PP);      // [2][32]

    int tid = threadIdx.x;
    int w = tid >> 5, n = tid & 31;

    unsigned long long trq[16];
    {
        const ulonglong2* tp = (const ulonglong2*)(transitions + n * TAGS);
#pragma unroll
        for (int p = 0; p < 8; p++) {
            ulonglong2 v = tp[p];
            trq[2 * p] = v.x; trq[2 * p + 1] = v.y;
        }
    }

    float fv = (n == START) ? 0.f : NEGV;

    for (int half = 0; half < 2; half++) {
        // ---- stage this half's feats into smem (all 1024 threads) ----
        {
            const float4* src = (const float4*)(g_feats + half * 1024 * TAGS);
            float4* dst = (float4*)fbuf;
            for (int i = tid; i < 1024 * 32 / 4; i += 1024) dst[i] = src[i];
        }
        __syncthreads();

        // ---- forward: warp 31 alone; others parked at next barrier ----
        if (w == 31) {
            int tbeg = half * 1024;
            float feat_cur = fbuf[0 * 32 + n];
            for (int ti = 0; ti < 1024; ti++) {
                int t = tbeg + ti;
                int pb = (t & 1) * 32;
                pp[pb + n] = fv;
                g_fv[t * TAGS + n] = fv;          // trajectory (fire-and-forget)
                __syncwarp();

                const ulonglong2* fq = (const ulonglong2*)(pp + pb);
                float m0, m1, m2, m3;
                {
                    ulonglong2 q0 = fq[0], q1 = fq[1];
                    unsigned long long s0, s1, s2, s3;
                    ADD2O(s0, q0.x, trq[0]);
                    ADD2O(s1, q0.y, trq[1]);
                    ADD2O(s2, q1.x, trq[2]);
                    ADD2O(s3, q1.y, trq[3]);
                    float a, b;
                    UNPK2(a, b, s0); m0 = fmaxf(a, b);
                    UNPK2(a, b, s1); m1 = fmaxf(a, b);
                    UNPK2(a, b, s2); m2 = fmaxf(a, b);
                    UNPK2(a, b, s3); m3 = fmaxf(a, b);
                }
#pragma unroll
                for (int p = 2; p < 8; p += 2) {
                    ulonglong2 qa = fq[p], qb = fq[p + 1];
                    unsigned long long s0, s1, s2, s3;
                    ADD2O(s0, qa.x, trq[2 * p]);
                    ADD2O(s1, qa.y, trq[2 * p + 1]);
                    ADD2O(s2, qb.x, trq[2 * p + 2]);
                    ADD2O(s3, qb.y, trq[2 * p + 3]);
                    float a, b;
                    UNPK2(a, b, s0); m0 = fmaxf(m0, a); m0 = fmaxf(m0, b);
                    UNPK2(a, b, s1); m1 = fmaxf(m1, a); m1 = fmaxf(m1, b);
                    UNPK2(a, b, s2); m2 = fmaxf(m2, a); m2 = fmaxf(m2, b);
                    UNPK2(a, b, s3); m3 = fmaxf(m3, a); m3 = fmaxf(m3, b);
                }
                float best = fmaxf(fmaxf(m0, m1), fmaxf(m2, m3));

                float feat_use = feat_cur;
                if (ti + 1 < 1024)
                    feat_cur = fbuf[(ti + 1) * 32 + n];   // LDS, hidden 1 ahead
                fv = best + feat_use;
            }
            if (half == 1) g_fv[T * TAGS + n] = fv;
        }
        __syncthreads();   // forward done before fbuf overwrite / phase 2
    }

    // ---------------- Phase 2: backpointers (all 32 warps, prefetched) -------
    {
        float tr[TAGS];
#pragma unroll
        for (int j = 0; j < TAGS; j++) tr[j] = transitions[n * TAGS + j];

        float* st = stage + w * TAGS;
        int tbeg = w * 64;
        float cur = __ldg(g_fv + (size_t)tbeg * TAGS + n);
        for (int t = tbeg; t < tbeg + 64; t++) {
            st[n] = cur;
            __syncwarp();
            float nxt = (t + 1 < tbeg + 64) ? __ldg(g_fv + (size_t)(t + 1) * TAGS + n) : 0.f;

            float bbest = st[0] + tr[0];
            int   barg  = 0;
#pragma unroll
            for (int j = 1; j < 32; j++) {
                float s = st[j] + tr[j];
                if (s > bbest) { bbest = s; barg = j; }
            }
            bp[t * TAGS + n] = (unsigned char)barg;
            __syncwarp();
            cur = nxt;
        }
    }

    __syncthreads();

    // ---------------- Phase 3: terminal + backtrack ----------------
    if (tid == 0) {
        int best = 0;
        float bb = g_fv[T * TAGS + 0] + transitions[STOP * TAGS + 0];
#pragma unroll
        for (int j = 1; j < TAGS; j++) {
            float v = g_fv[T * TAGS + j] + transitions[STOP * TAGS + j];
            if (v > bb) { bb = v; best = j; }
        }
        float score = g_fv[T * TAGS + best] + transitions[STOP * TAGS + best];

        if (out_size >= T + 1) {
            out[0] = score;
            int tag = best;
            for (int t = T - 1; t >= 0; t--) {
                out[1 + t] = (float)tag;
                tag = bp[t * TAGS + tag];
            }
        } else if (out_size >= T) {
            int tag = best;
            for (int t = T - 1; t >= 0; t--) {
                out[t] = (float)tag;
                tag = bp[t * TAGS + tag];
            }
        } else {
            out[0] = score;
        }
    }
}

// ---------------- launch ----------------
extern "C" void kernel_launch(void* const* d_in, const int* in_sizes, int n_in,
                              void* d_out, int out_size) {
    const int*   sentence    = (const int*)d_in[0];
    const float* emb         = (const float*)d_in[1];
    const float* w_ih_f      = (const float*)d_in[2];
    const float* w_hh_f      = (const float*)d_in[3];
    const float* b_f         = (const float*)d_in[4];
    const float* w_ih_b      = (const float*)d_in[5];
    const float* w_hh_b      = (const float*)d_in[6];
    const float* b_b         = (const float*)d_in[7];
    const float* W_out       = (const float*)d_in[8];
    const float* b_out       = (const float*)d_in[9];
    const float* transitions = (const float*)d_in[10];
    const float* h0          = (const float*)d_in[11];
    const float* c0          = (const float*)d_in[12];
    float* out = (float*)d_out;

    k_prep<<<T + 2048, 128>>>(sentence, emb);
    k_gemm<<<dim3(16, 16, 2), 256>>>(w_ih_f, b_f, w_ih_b, b_b);
    k_lstm<<<128, 288>>>(w_hh_f, w_hh_b, h0, c0);
    k_feats<<<128, 512>>>(W_out, b_out);

    cudaFuncSetAttribute(k_vit, cudaFuncAttributeMaxDynamicSharedMemorySize, VSM_TOTAL);
    k_vit<<<148, 1024, VSM_TOTAL>>>(transitions, out, out_size);
}